// round 16
// baseline (speedup 1.0000x reference)
#include <cuda_runtime.h>
#include <cuda_bf16.h>
#include <cstdint>

#define HH   128
#define LBn  64
#define PWn  32
#define WLn  96
#define WC   65
#define WCP  68      // padded T width (17 float4 groups); pad cols stay 0
#define NCTA 64
#define TPB  256

// ---------------- device scratch (no allocations allowed) ----------------
__device__ float g_FT[WLn * HH * HH];
__device__ float g_Pp[2][HH * HH];        // Ppred (pre-update covariance)
__device__ float g_Tg[2][HH * WCP];       // T (pre-update influence), padded
__device__ float g_vpart[2][NCTA][HH];    // partials of v = h^T Ppred
__device__ float g_qpart[2][NCTA][WCP];   // partials of q = h^T T
__device__ float g_urow[2][HH];           // u = Ppred h (full row vector)
__device__ float g_Wcf[HH * WCP];         // corrected Wc after filter step 63
__device__ float g_V[PWn][WCP];
// Tree-barrier state: monotonic counters (no per-barrier reset); padded to
// separate cache lines. Zeroed between graph replays by pred_chains.
__device__ unsigned int g_gcnt[8][32];
__device__ unsigned int g_rcnt;
__device__ unsigned int g_gen;

__device__ __forceinline__ float comp2(float2 v, int h) { return h ? v.y : v.x; }

// Atomic acquire load (NOT an RMW: no LTS atomic-ALU serialization).
__device__ __forceinline__ unsigned int ldacq_u32(const unsigned int* p) {
    unsigned int v;
    asm volatile("ld.global.acquire.gpu.u32 %0, [%1];" : "=r"(v) : "l"(p) : "memory");
    return v;
}

// Hierarchical grid barrier, ABSOLUTE generation n (0-based).
// 8 groups x 8 CTAs: arrive = counting RMW on my GROUP word (8 serialized
// RMWs, not 64); group's last arriver (old == n*8+7, monotonic counter: no
// reset, no reset-race) arrives at the root word; root's last arriver bumps
// g_gen. Wait = single-word g_gen acquire-load poll, exactly as the proven
// round-9/15 protocol (monotonic: stale reads only poll longer).
// __threadfence() (CCTL.IVALL) after makes other SMs' plain stores visible.
__device__ __forceinline__ void gbar(unsigned int n, int c) {
    __syncthreads();
    if (threadIdx.x == 0) {
        const unsigned int tgt = n * 8u + 7u;
        __threadfence();
        unsigned int a = atomicAdd(&g_gcnt[c >> 3][0], 1u);
        if (a == tgt) {
            unsigned int b = atomicAdd(&g_rcnt, 1u);
            if (b == tgt) {
                __threadfence();
                atomicExch(&g_gen, n + 1u);
            } else {
                while ((int)(ldacq_u32(&g_gen) - (n + 1u)) < 0) { __nanosleep(64); }
            }
        } else {
            while ((int)(ldacq_u32(&g_gen) - (n + 1u)) < 0) { __nanosleep(64); }
        }
        __threadfence();
    }
    __syncthreads();
}

// ---------------------------------------------------------------------------
// Kernel 1: transpose the 96 F matrices (128x128) into g_FT.
// ---------------------------------------------------------------------------
__global__ void __launch_bounds__(256) transpose_f(const float* __restrict__ Fw) {
    const int t  = blockIdx.x;
    const int ti = blockIdx.y;
    __shared__ float s[32][33];
    const float* src = Fw + (size_t)t * HH * HH;
    float* dst = g_FT + (size_t)t * HH * HH;
    const int x  = threadIdx.x & 31;
    const int y0 = threadIdx.x >> 5;
    for (int tj = 0; tj < 4; tj++) {
        #pragma unroll
        for (int yy = 0; yy < 32; yy += 8)
            s[y0 + yy][x] = src[(ti * 32 + y0 + yy) * HH + tj * 32 + x];
        __syncthreads();
        #pragma unroll
        for (int yy = 0; yy < 32; yy += 8)
            dst[(tj * 32 + y0 + yy) * HH + ti * 32 + x] = s[x][y0 + yy];
        __syncthreads();
    }
}

// ---------------------------------------------------------------------------
// Kernel 2: persistent Kalman FILTER — EXACT round-15 structure (proven at
// 441us: LDG.128 k-loops, hoisted reductions, deferred rank-1 algebra);
// ONLY change: hierarchical arrive in the grid barrier.
//   k-loop layout: jg = tid&31 -> columns J0=4jg..4jg+3 ; h = tid>>5 ->
//     k-eighth [16h,16h+16). Warp = one h; 512B coalesced float4 loads.
//   epilogue layout: jO = tid&127, hO = tid>>7 owns (row 2c+hO, col jO).
// Deferred rank-1:
//   F*P_new = F*Ppred - (F*u/S) v^T ;  F*Wc_new = F*T - (F*u/S) q~^T
//   S = R + sum_j h[j] u[j]   (Ppred NOT symmetric: u != v)
// ---------------------------------------------------------------------------
__global__ void __launch_bounds__(TPB, 1) kalman_persist(
    const float* __restrict__ Fw, const float* __restrict__ Fb,
    const float* __restrict__ Hw, const float* __restrict__ Hb,
    const float* __restrict__ istate, const float* __restrict__ icov,
    const float* __restrict__ Q, const float* __restrict__ R)
{
    const int c = blockIdx.x, tid = threadIdx.x;
    // k-loop layout
    const int jg = tid & 31, h = tid >> 5;     // J0..J0+3 cols, k-eighth h
    const int J0 = jg * 4;
    const int k0 = h * 16;
    const bool doTg = (jg < 17);               // T column groups (0..67)
    // epilogue layout
    const int jO = tid & 127, hO = tid >> 7;
    const int row0 = c * 2;
    const int myrowO = row0 + hO;
    const bool doTO = (jO < WCP);
    const int wO = (tid >> 5) & 3;             // warp-in-half for sred

    __shared__ float  sh[2][HH];       // H_w rows, double buffered
    __shared__ float2 sF[2][HH];       // owned F rows (k-major), dbl buffered
    __shared__ float  sfbh[2][4];      // [buf][0..1]=F_b rows, [2]=H_b
    __shared__ float2 sA1p[8][HH];     // raw A1 partials per k-eighth
    __shared__ float2 sTp[8][WCP];     // raw T partials
    __shared__ float2 sPp[8][HH];      // loopB partials
    __shared__ float2 sA[HH];          // corrected A1
    __shared__ float  svp8[8][HH];     // v-reduction partials (8-way)
    __shared__ float  sqs8[8][WCP];    // q-reduction partials (8-way)
    __shared__ float4 su4[32];         // u staging (prefetched)
    __shared__ float  svp[2][HH];      // epilogue v staging
    __shared__ float  sqs[2][WCP];     // epilogue q staging
    __shared__ float  sred[2][3][4];   // [half][S,FK0,FK1][warp]
    __shared__ float  sured[2][4];     // u partials [half][warp]

    // ---- init ----
    const float qreg = Q[myrowO * HH + jO];    // Q step-invariant: 1 load
    const float R0 = R[0];
    g_Pp[0][myrowO * HH + jO] = icov[myrowO * HH + jO];
    if (doTO)
        g_Tg[0][myrowO * WCP + jO] = (jO == 0) ? istate[myrowO] : 0.f;
    // step-0 params into buffer 0
    if (tid < HH) {
        sh[0][tid] = Hw[tid];
        sF[0][tid] = make_float2(Fw[(size_t)row0 * HH + tid],
                                 Fw[(size_t)(row0 + 1) * HH + tid]);
    } else if (tid < HH + 2) {
        sfbh[0][tid - HH] = Fb[row0 + (tid - HH)];
    } else if (tid == HH + 2) {
        sfbh[0][2] = Hb[0];
    }
    int cur = 0, pb = 0;
    unsigned int nbar = 0;
    gbar(nbar++, c);

    // ======================= filter (64 steps) =======================
    for (int t = 0; t < LBn; t++) {
        const bool corr = (t >= 1);
        const float hbprev = sfbh[pb ^ 1][2];

        // ---- v/q partial reductions (float4, 8-way over CTAs) + u fetch ----
        float4 vs4 = make_float4(0.f, 0.f, 0.f, 0.f);
        float4 qs4 = make_float4(0.f, 0.f, 0.f, 0.f);
        float4 uld = make_float4(0.f, 0.f, 0.f, 0.f);
        if (corr) {
            const int cc0 = h * 8;
            #pragma unroll
            for (int i = 0; i < 8; i++) {
                float4 vv = *(const float4*)&g_vpart[cur][cc0 + i][J0];
                vs4.x += vv.x; vs4.y += vv.y; vs4.z += vv.z; vs4.w += vv.w;
            }
            if (doTg) {
                #pragma unroll
                for (int i = 0; i < 8; i++) {
                    float4 qq = *(const float4*)&g_qpart[cur][cc0 + i][J0];
                    qs4.x += qq.x; qs4.y += qq.y; qs4.z += qq.z; qs4.w += qq.w;
                }
            }
            if (h == 0) uld = *(const float4*)&g_urow[cur][J0];
        }

        // ---- raw loops (float4): A1 = F*Ppred_prev, Traw = F*T_prev ----
        float a0[4] = {0.f,0.f,0.f,0.f}, a1v[4] = {0.f,0.f,0.f,0.f};
        float t0v[4] = {0.f,0.f,0.f,0.f}, t1v[4] = {0.f,0.f,0.f,0.f};
        {
            const float* Pc = g_Pp[cur] + (size_t)k0 * HH + J0;
            const float* Tc = g_Tg[cur] + (size_t)k0 * WCP + J0;
            #pragma unroll
            for (int kk = 0; kk < 16; kk++) {
                float2 f = sF[pb][k0 + kk];
                float4 p = *(const float4*)(Pc + kk * HH);
                a0[0] += f.x * p.x; a0[1] += f.x * p.y;
                a0[2] += f.x * p.z; a0[3] += f.x * p.w;
                a1v[0] += f.y * p.x; a1v[1] += f.y * p.y;
                a1v[2] += f.y * p.z; a1v[3] += f.y * p.w;
                if (doTg) {
                    float4 w4 = *(const float4*)(Tc + kk * WCP);
                    t0v[0] += f.x * w4.x; t0v[1] += f.x * w4.y;
                    t0v[2] += f.x * w4.z; t0v[3] += f.x * w4.w;
                    t1v[0] += f.y * w4.x; t1v[1] += f.y * w4.y;
                    t1v[2] += f.y * w4.z; t1v[3] += f.y * w4.w;
                }
            }
        }
        #pragma unroll
        for (int i = 0; i < 4; i++) {
            sA1p[h][J0 + i] = make_float2(a0[i], a1v[i]);
            if (doTg) sTp[h][J0 + i] = make_float2(t0v[i], t1v[i]);
        }
        *(float4*)&svp8[h][J0] = vs4;
        if (doTg) *(float4*)&sqs8[h][J0] = qs4;
        if (h == 0) su4[jg] = uld;
        __syncthreads();

        // ======== epilogue layout (jO, hO) — round-9 algebra ========
        float v_j = 0.f, qsum = 0.f;
        #pragma unroll
        for (int q = 0; q < 8; q++) v_j += svp8[q][jO];
        if (doTO) {
            #pragma unroll
            for (int q = 0; q < 8; q++) qsum += sqs8[q][jO];
        }
        const float uval = ((const float*)su4)[jO];

        float termS = 0.f, tf0 = 0.f, tf1 = 0.f;
        if (corr) {
            termS = sh[pb ^ 1][jO] * uval;        // h_{t-1}[j] * u[j]
            float2 f = sF[pb][jO];                 // F_t rows at k=jO
            tf0 = f.x * uval; tf1 = f.y * uval;
        }
        #pragma unroll
        for (int o = 16; o > 0; o >>= 1) {
            termS += __shfl_xor_sync(0xffffffffu, termS, o);
            tf0   += __shfl_xor_sync(0xffffffffu, tf0, o);
            tf1   += __shfl_xor_sync(0xffffffffu, tf1, o);
        }
        if ((tid & 31) == 0) {
            sred[hO][0][wO] = termS; sred[hO][1][wO] = tf0; sred[hO][2][wO] = tf1;
        }
        __syncthreads();

        float FK0 = 0.f, FK1 = 0.f;
        if (corr) {
            float S = R0 + sred[hO][0][0] + sred[hO][0][1]
                         + sred[hO][0][2] + sred[hO][0][3];
            float inv = 1.f / S;
            FK0 = (sred[hO][1][0] + sred[hO][1][1]
                 + sred[hO][1][2] + sred[hO][1][3]) * inv;
            FK1 = (sred[hO][2][0] + sred[hO][2][1]
                 + sred[hO][2][2] + sred[hO][2][3]) * inv;
        }
        float qt = 0.f;
        if (corr && doTO)
            qt = qsum + (jO == 0 ? hbprev : 0.f) - (jO == t ? 1.f : 0.f);

        // corrected A1 (right vector is v, NOT u)
        if (hO == 0) {
            float A1r0 = 0.f, A1r1 = 0.f;
            #pragma unroll
            for (int q = 0; q < 8; q++) {
                float2 vq = sA1p[q][jO];
                A1r0 += vq.x; A1r1 += vq.y;
            }
            sA[jO] = make_float2(A1r0 - FK0 * v_j, A1r1 - FK1 * v_j);
        }
        float Tval = 0.f;
        if (doTO) {
            float Tr = 0.f;
            #pragma unroll
            for (int q = 0; q < 8; q++) Tr += comp2(sTp[q][jO], hO);
            Tval = Tr - (hO ? FK1 : FK0) * qt;
            if (jO == 0) Tval += sfbh[pb][hO];
        }
        __syncthreads();

        // ---- loopB (float4): Ppred = A1 * F^T + Q ----
        float p0[4] = {0.f,0.f,0.f,0.f}, p1[4] = {0.f,0.f,0.f,0.f};
        {
            const float* FTt = g_FT + (size_t)t * HH * HH + (size_t)k0 * HH + J0;
            #pragma unroll
            for (int kk = 0; kk < 16; kk++) {
                float2 a = sA[k0 + kk];
                float4 ft = *(const float4*)(FTt + kk * HH);
                p0[0] += a.x * ft.x; p0[1] += a.x * ft.y;
                p0[2] += a.x * ft.z; p0[3] += a.x * ft.w;
                p1[0] += a.y * ft.x; p1[1] += a.y * ft.y;
                p1[2] += a.y * ft.z; p1[3] += a.y * ft.w;
            }
        }
        #pragma unroll
        for (int i = 0; i < 4; i++)
            sPp[h][J0 + i] = make_float2(p0[i], p1[i]);
        __syncthreads();

        // ---- final combine + writes (jO, hO) ----
        float ppf = qreg;
        #pragma unroll
        for (int q = 0; q < 8; q++) ppf += comp2(sPp[q][jO], hO);

        const int nxt = cur ^ 1;
        g_Pp[nxt][myrowO * HH + jO] = ppf;
        if (doTO) g_Tg[nxt][myrowO * WCP + jO] = Tval;
        const float hr = sh[pb][myrowO];
        svp[hO][jO] = hr * ppf;
        if (doTO) sqs[hO][jO] = hr * Tval;
        // u[myrowO] = sum_j ppf * h_t[j]
        {
            float uv = ppf * sh[pb][jO];
            #pragma unroll
            for (int o = 16; o > 0; o >>= 1)
                uv += __shfl_xor_sync(0xffffffffu, uv, o);
            if ((tid & 31) == 0) sured[hO][wO] = uv;
        }
        __syncthreads();
        if (tid < HH)
            g_vpart[nxt][c][tid] = svp[0][tid] + svp[1][tid];
        else if (tid - HH < WCP)
            g_qpart[nxt][c][tid - HH] = sqs[0][tid - HH] + sqs[1][tid - HH];
        if (jO == 0)
            g_urow[nxt][myrowO] = sured[hO][0] + sured[hO][1]
                                + sured[hO][2] + sured[hO][3];

        // ---- prefetch step t+1 params (ordered by gbar's entry sync) ----
        {
            const int t1 = t + 1, nb = pb ^ 1;
            if (tid < HH) {
                sh[nb][tid] = Hw[t1 * HH + tid];
                sF[nb][tid] = make_float2(Fw[((size_t)t1 * HH + row0) * HH + tid],
                                          Fw[((size_t)t1 * HH + row0 + 1) * HH + tid]);
            } else if (tid < HH + 2) {
                sfbh[nb][tid - HH] = Fb[t1 * HH + row0 + (tid - HH)];
            } else if (tid == HH + 2) {
                sfbh[nb][2] = Hb[t1];
            }
        }

        gbar(nbar++, c);
        cur ^= 1; pb ^= 1;
    }

    // ---- materialize Wcf = T_63 - (u/S) q~^T  (jO, hO layout) ----
    {
        const float hb63 = sfbh[pb ^ 1][2];
        const float uj = g_urow[cur][jO];
        float termS = sh[pb ^ 1][jO] * uj;
        #pragma unroll
        for (int o = 16; o > 0; o >>= 1)
            termS += __shfl_xor_sync(0xffffffffu, termS, o);
        if ((tid & 31) == 0) sred[hO][0][wO] = termS;
        float qs = 0.f;
        if (doTO) {
            const int cc0 = hO * 32;
            #pragma unroll
            for (int i = 0; i < 32; i++) qs += g_qpart[cur][cc0 + i][jO];
            sqs[hO][jO] = qs;
        }
        __syncthreads();
        const float S = R0 + sred[hO][0][0] + sred[hO][0][1]
                           + sred[hO][0][2] + sred[hO][0][3];
        if (doTO) {
            const float Krow = g_urow[cur][myrowO] / S;
            const float qt = sqs[0][jO] + sqs[1][jO]
                           + (jO == 0 ? hb63 : 0.f) - (jO == LBn ? 1.f : 0.f);
            g_Wcf[myrowO * WCP + jO] = g_Tg[cur][myrowO * WCP + jO] - Krow * qt;
        }
    }
}

// ---------------------------------------------------------------------------
// Kernel 3: prediction chains — CTA m computes V row m with NO grid barriers.
// Also resets the tree-barrier counters for the next graph replay.
// ---------------------------------------------------------------------------
__global__ void __launch_bounds__(256) pred_chains(
    const float* __restrict__ Fw, const float* __restrict__ Fb,
    const float* __restrict__ Hw, const float* __restrict__ Hb)
{
    const int m = blockIdx.x;
    const int tid = threadIdx.x;
    const int j = tid & 127, h = tid >> 7;
    const int k0 = h * 64;

    // reset barrier state (persist kernel fully completed in stream order)
    if (m == 0) {
        if (tid == 0) { g_gen = 0u; g_rcnt = 0u; }
        if (tid < 8) g_gcnt[tid][0] = 0u;
    }

    __shared__ float r[2][HH];
    __shared__ float rp[2][HH];
    __shared__ float sfb[HH];
    __shared__ float sbias[2];

    if (tid < HH) r[0][tid] = Hw[(LBn + m) * HH + tid];
    float bias = Hb[LBn + m];
    __syncthreads();

    int rb = 0;
    for (int i = LBn + m; i >= LBn; --i) {
        if (tid < HH) sfb[tid] = Fb[i * HH + tid];
        __syncthreads();
        float rn = 0.f, bp = 0.f;
        const float* Fi = Fw + (size_t)i * HH * HH + (size_t)k0 * HH + j;
        #pragma unroll 16
        for (int kk = 0; kk < 64; kk++) {
            float rk = r[rb][k0 + kk];
            rn += Fi[kk * HH] * rk;
            bp += sfb[k0 + kk] * rk;
        }
        rp[h][j] = rn;
        if (j == 0) sbias[h] = bp;
        __syncthreads();
        if (tid < HH) r[rb ^ 1][tid] = rp[0][tid] + rp[1][tid];
        bias += sbias[0] + sbias[1];
        __syncthreads();
        rb ^= 1;
    }

    if (j < WC) {
        float vn = 0.f;
        const float* Wf = g_Wcf + (size_t)k0 * WCP + j;
        #pragma unroll 16
        for (int kk = 0; kk < 64; kk++)
            vn += Wf[kk * WCP] * r[rb][k0 + kk];
        rp[h][j] = vn;
    }
    __syncthreads();
    if (tid < WC) {
        float s = rp[0][tid] + rp[1][tid];
        if (tid == 0) s += bias;
        g_V[m][tid] = s;
    }
}

// ---------------------------------------------------------------------------
// Kernel 4: out[b][p] = V[p][0] + sum_t V[p][1+t] x[b][t]
// ---------------------------------------------------------------------------
__global__ void __launch_bounds__(256) out_gemm(
    const float* __restrict__ x, float* __restrict__ out)
{
    __shared__ float sV[PWn][WC];
    __shared__ float sx[8][LBn];
    const int tid = threadIdx.x;
    const int b0 = blockIdx.x * 8;

    for (int e = tid; e < PWn * WC; e += 256) {
        int p = e / WC, jj = e % WC;
        sV[p][jj] = g_V[p][jj];
    }
    if (tid < 128) {
        const int row = tid >> 4, seg = tid & 15;
        float4 v = *(const float4*)(x + (size_t)(b0 + row) * LBn + seg * 4);
        sx[row][seg * 4 + 0] = v.x; sx[row][seg * 4 + 1] = v.y;
        sx[row][seg * 4 + 2] = v.z; sx[row][seg * 4 + 3] = v.w;
    }
    __syncthreads();

    const int w = tid >> 5, p = tid & 31;
    float acc = sV[p][0];
    #pragma unroll 16
    for (int tt = 0; tt < LBn; tt++)
        acc += sV[p][1 + tt] * sx[w][tt];
    out[(size_t)(b0 + w) * PWn + p] = acc;
}

// ---------------------------------------------------------------------------
extern "C" void kernel_launch(void* const* d_in, const int* in_sizes, int n_in,
                              void* d_out, int out_size) {
    const float* x   = (const float*)d_in[0];
    const float* Fw  = (const float*)d_in[1];
    const float* Fb  = (const float*)d_in[2];
    const float* Hw  = (const float*)d_in[3];
    const float* Hb  = (const float*)d_in[4];
    const float* ist = (const float*)d_in[5];
    const float* icv = (const float*)d_in[6];
    const float* Q   = (const float*)d_in[7];
    const float* R   = (const float*)d_in[8];

    dim3 tgrid(WLn, 4);
    transpose_f<<<tgrid, 256>>>(Fw);
    kalman_persist<<<NCTA, TPB>>>(Fw, Fb, Hw, Hb, ist, icv, Q, R);
    pred_chains<<<PWn, 256>>>(Fw, Fb, Hw, Hb);
    out_gemm<<<8192 / 8, 256>>>(x, (float*)d_out);
}

// round 17
// speedup vs baseline: 1.0656x; 1.0656x over previous
#include <cuda_runtime.h>
#include <cuda_bf16.h>
#include <cstdint>

#define HH   128
#define LBn  64
#define PWn  32
#define WLn  96
#define WC   65
#define WCP  68      // padded T width (17 float4 groups); pad cols stay 0
#define NCTA 64
#define TPB  256

// ---------------- device scratch (no allocations allowed) ----------------
__device__ float g_FT[WLn * HH * HH];
__device__ float g_Pp[2][HH * HH];        // Ppred (pre-update covariance)
__device__ float g_Tg[2][HH * WCP];       // T (pre-update influence), padded
__device__ float g_vpart[2][NCTA][HH];    // partials of v = h^T Ppred
__device__ float g_qpart[2][NCTA][WCP];   // partials of q = h^T T
__device__ float g_urow[2][HH];           // u = Ppred h (full row vector)
__device__ float g_Wcf[HH * WCP];         // corrected Wc after filter step 63
__device__ float g_V[PWn][WCP];
__device__ unsigned int g_cnt;   // zero-init; self-resetting
__device__ unsigned int g_gen;   // zero-init; reset by pred_chains each run

__device__ __forceinline__ float comp2(float2 v, int h) { return h ? v.y : v.x; }

// Atomic acquire load (NOT an RMW: no LTS atomic-ALU serialization).
__device__ __forceinline__ unsigned int ldacq_u32(const unsigned int* p) {
    unsigned int v;
    asm volatile("ld.global.acquire.gpu.u32 %0, [%1];" : "=r"(v) : "l"(p) : "memory");
    return v;
}

// Grid barrier, ABSOLUTE generation n — EXACT round-9/15 protocol (proven):
// arrive = counting RMW on one word; release = last arriver bumps g_gen;
// wait = single-word acquire-load poll (monotonic: stale reads only poll
// longer). __threadfence() (CCTL.IVALL) after makes other SMs' plain stores
// visible to plain loads. Flat arrive beats hierarchical (round-16 evidence:
// tree adds a serialized release round-trip, +20us).
__device__ __forceinline__ void gbar(unsigned int n) {
    __syncthreads();
    if (threadIdx.x == 0) {
        __threadfence();
        unsigned int a = atomicAdd(&g_cnt, 1u);
        if (a == NCTA - 1u) {
            atomicExch(&g_cnt, 0u);                // reset BEFORE release
            __threadfence();
            atomicExch(&g_gen, n + 1u);
        } else {
            while ((int)(ldacq_u32(&g_gen) - (n + 1u)) < 0) { __nanosleep(32); }
        }
        __threadfence();
    }
    __syncthreads();
}

// ---------------------------------------------------------------------------
// Kernel 1: transpose the 96 F matrices (128x128) into g_FT.
// ---------------------------------------------------------------------------
__global__ void __launch_bounds__(256) transpose_f(const float* __restrict__ Fw) {
    const int t  = blockIdx.x;
    const int ti = blockIdx.y;
    __shared__ float s[32][33];
    const float* src = Fw + (size_t)t * HH * HH;
    float* dst = g_FT + (size_t)t * HH * HH;
    const int x  = threadIdx.x & 31;
    const int y0 = threadIdx.x >> 5;
    for (int tj = 0; tj < 4; tj++) {
        #pragma unroll
        for (int yy = 0; yy < 32; yy += 8)
            s[y0 + yy][x] = src[(ti * 32 + y0 + yy) * HH + tj * 32 + x];
        __syncthreads();
        #pragma unroll
        for (int yy = 0; yy < 32; yy += 8)
            dst[(tj * 32 + y0 + yy) * HH + ti * 32 + x] = s[x][y0 + yy];
        __syncthreads();
    }
}

// ---------------------------------------------------------------------------
// Kernel 2: persistent Kalman FILTER — round-15 structure (proven 441us);
// ONLY change: FT tile loads hoisted to the step top (g_FT is step-constant,
// independent of the barrier), so loop B's L2 latency hides behind loop A +
// epilogue. Loop B consumes the prefetched registers.
//   k-loop layout: jg = tid&31 -> cols J0=4jg..4jg+3 ; h = tid>>5 ->
//     k-eighth [16h,16h+16). 512B coalesced float4 loads.
//   epilogue layout: jO = tid&127, hO = tid>>7 owns (row 2c+hO, col jO).
// Deferred rank-1:
//   F*P_new = F*Ppred - (F*u/S) v^T ;  F*Wc_new = F*T - (F*u/S) q~^T
//   S = R + sum_j h[j] u[j]   (Ppred NOT symmetric: u != v)
// ---------------------------------------------------------------------------
__global__ void __launch_bounds__(TPB, 1) kalman_persist(
    const float* __restrict__ Fw, const float* __restrict__ Fb,
    const float* __restrict__ Hw, const float* __restrict__ Hb,
    const float* __restrict__ istate, const float* __restrict__ icov,
    const float* __restrict__ Q, const float* __restrict__ R)
{
    const int c = blockIdx.x, tid = threadIdx.x;
    // k-loop layout
    const int jg = tid & 31, h = tid >> 5;     // J0..J0+3 cols, k-eighth h
    const int J0 = jg * 4;
    const int k0 = h * 16;
    const bool doTg = (jg < 17);               // T column groups (0..67)
    // epilogue layout
    const int jO = tid & 127, hO = tid >> 7;
    const int row0 = c * 2;
    const int myrowO = row0 + hO;
    const bool doTO = (jO < WCP);
    const int wO = (tid >> 5) & 3;             // warp-in-half for sred

    __shared__ float  sh[2][HH];       // H_w rows, double buffered
    __shared__ float2 sF[2][HH];       // owned F rows (k-major), dbl buffered
    __shared__ float  sfbh[2][4];      // [buf][0..1]=F_b rows, [2]=H_b
    __shared__ float2 sA1p[8][HH];     // raw A1 partials per k-eighth
    __shared__ float2 sTp[8][WCP];     // raw T partials
    __shared__ float2 sPp[8][HH];      // loopB partials
    __shared__ float2 sA[HH];          // corrected A1
    __shared__ float  svp8[8][HH];     // v-reduction partials (8-way)
    __shared__ float  sqs8[8][WCP];    // q-reduction partials (8-way)
    __shared__ float4 su4[32];         // u staging (prefetched)
    __shared__ float  svp[2][HH];      // epilogue v staging
    __shared__ float  sqs[2][WCP];     // epilogue q staging
    __shared__ float  sred[2][3][4];   // [half][S,FK0,FK1][warp]
    __shared__ float  sured[2][4];     // u partials [half][warp]

    // ---- init ----
    const float qreg = Q[myrowO * HH + jO];    // Q step-invariant: 1 load
    const float R0 = R[0];
    g_Pp[0][myrowO * HH + jO] = icov[myrowO * HH + jO];
    if (doTO)
        g_Tg[0][myrowO * WCP + jO] = (jO == 0) ? istate[myrowO] : 0.f;
    // step-0 params into buffer 0
    if (tid < HH) {
        sh[0][tid] = Hw[tid];
        sF[0][tid] = make_float2(Fw[(size_t)row0 * HH + tid],
                                 Fw[(size_t)(row0 + 1) * HH + tid]);
    } else if (tid < HH + 2) {
        sfbh[0][tid - HH] = Fb[row0 + (tid - HH)];
    } else if (tid == HH + 2) {
        sfbh[0][2] = Hb[0];
    }
    int cur = 0, pb = 0;
    unsigned int nbar = 0;
    gbar(nbar++);

    // ======================= filter (64 steps) =======================
    for (int t = 0; t < LBn; t++) {
        const bool corr = (t >= 1);
        const float hbprev = sfbh[pb ^ 1][2];

        // ---- FT prefetch (step-constant; independent of barrier data):
        //      issue first so its L2 latency hides behind loop A+epilogue ----
        float4 ftr[16];
        {
            const float* FTt = g_FT + (size_t)t * HH * HH + (size_t)k0 * HH + J0;
            #pragma unroll
            for (int kk = 0; kk < 16; kk++)
                ftr[kk] = *(const float4*)(FTt + kk * HH);
        }

        // ---- v/q partial reductions (float4, 8-way over CTAs) + u fetch ----
        float4 vs4 = make_float4(0.f, 0.f, 0.f, 0.f);
        float4 qs4 = make_float4(0.f, 0.f, 0.f, 0.f);
        float4 uld = make_float4(0.f, 0.f, 0.f, 0.f);
        if (corr) {
            const int cc0 = h * 8;
            #pragma unroll
            for (int i = 0; i < 8; i++) {
                float4 vv = *(const float4*)&g_vpart[cur][cc0 + i][J0];
                vs4.x += vv.x; vs4.y += vv.y; vs4.z += vv.z; vs4.w += vv.w;
            }
            if (doTg) {
                #pragma unroll
                for (int i = 0; i < 8; i++) {
                    float4 qq = *(const float4*)&g_qpart[cur][cc0 + i][J0];
                    qs4.x += qq.x; qs4.y += qq.y; qs4.z += qq.z; qs4.w += qq.w;
                }
            }
            if (h == 0) uld = *(const float4*)&g_urow[cur][J0];
        }

        // ---- raw loops (float4): A1 = F*Ppred_prev, Traw = F*T_prev ----
        float a0[4] = {0.f,0.f,0.f,0.f}, a1v[4] = {0.f,0.f,0.f,0.f};
        float t0v[4] = {0.f,0.f,0.f,0.f}, t1v[4] = {0.f,0.f,0.f,0.f};
        {
            const float* Pc = g_Pp[cur] + (size_t)k0 * HH + J0;
            const float* Tc = g_Tg[cur] + (size_t)k0 * WCP + J0;
            #pragma unroll
            for (int kk = 0; kk < 16; kk++) {
                float2 f = sF[pb][k0 + kk];
                float4 p = *(const float4*)(Pc + kk * HH);
                a0[0] += f.x * p.x; a0[1] += f.x * p.y;
                a0[2] += f.x * p.z; a0[3] += f.x * p.w;
                a1v[0] += f.y * p.x; a1v[1] += f.y * p.y;
                a1v[2] += f.y * p.z; a1v[3] += f.y * p.w;
                if (doTg) {
                    float4 w4 = *(const float4*)(Tc + kk * WCP);
                    t0v[0] += f.x * w4.x; t0v[1] += f.x * w4.y;
                    t0v[2] += f.x * w4.z; t0v[3] += f.x * w4.w;
                    t1v[0] += f.y * w4.x; t1v[1] += f.y * w4.y;
                    t1v[2] += f.y * w4.z; t1v[3] += f.y * w4.w;
                }
            }
        }
        #pragma unroll
        for (int i = 0; i < 4; i++) {
            sA1p[h][J0 + i] = make_float2(a0[i], a1v[i]);
            if (doTg) sTp[h][J0 + i] = make_float2(t0v[i], t1v[i]);
        }
        *(float4*)&svp8[h][J0] = vs4;
        if (doTg) *(float4*)&sqs8[h][J0] = qs4;
        if (h == 0) su4[jg] = uld;
        __syncthreads();

        // ======== epilogue layout (jO, hO) — round-9 algebra ========
        float v_j = 0.f, qsum = 0.f;
        #pragma unroll
        for (int q = 0; q < 8; q++) v_j += svp8[q][jO];
        if (doTO) {
            #pragma unroll
            for (int q = 0; q < 8; q++) qsum += sqs8[q][jO];
        }
        const float uval = ((const float*)su4)[jO];

        float termS = 0.f, tf0 = 0.f, tf1 = 0.f;
        if (corr) {
            termS = sh[pb ^ 1][jO] * uval;        // h_{t-1}[j] * u[j]
            float2 f = sF[pb][jO];                 // F_t rows at k=jO
            tf0 = f.x * uval; tf1 = f.y * uval;
        }
        #pragma unroll
        for (int o = 16; o > 0; o >>= 1) {
            termS += __shfl_xor_sync(0xffffffffu, termS, o);
            tf0   += __shfl_xor_sync(0xffffffffu, tf0, o);
            tf1   += __shfl_xor_sync(0xffffffffu, tf1, o);
        }
        if ((tid & 31) == 0) {
            sred[hO][0][wO] = termS; sred[hO][1][wO] = tf0; sred[hO][2][wO] = tf1;
        }
        __syncthreads();

        float FK0 = 0.f, FK1 = 0.f;
        if (corr) {
            float S = R0 + sred[hO][0][0] + sred[hO][0][1]
                         + sred[hO][0][2] + sred[hO][0][3];
            float inv = 1.f / S;
            FK0 = (sred[hO][1][0] + sred[hO][1][1]
                 + sred[hO][1][2] + sred[hO][1][3]) * inv;
            FK1 = (sred[hO][2][0] + sred[hO][2][1]
                 + sred[hO][2][2] + sred[hO][2][3]) * inv;
        }
        float qt = 0.f;
        if (corr && doTO)
            qt = qsum + (jO == 0 ? hbprev : 0.f) - (jO == t ? 1.f : 0.f);

        // corrected A1 (right vector is v, NOT u)
        if (hO == 0) {
            float A1r0 = 0.f, A1r1 = 0.f;
            #pragma unroll
            for (int q = 0; q < 8; q++) {
                float2 vq = sA1p[q][jO];
                A1r0 += vq.x; A1r1 += vq.y;
            }
            sA[jO] = make_float2(A1r0 - FK0 * v_j, A1r1 - FK1 * v_j);
        }
        float Tval = 0.f;
        if (doTO) {
            float Tr = 0.f;
            #pragma unroll
            for (int q = 0; q < 8; q++) Tr += comp2(sTp[q][jO], hO);
            Tval = Tr - (hO ? FK1 : FK0) * qt;
            if (jO == 0) Tval += sfbh[pb][hO];
        }
        __syncthreads();

        // ---- loopB: Ppred = A1 * F^T + Q (FT already in registers) ----
        float p0[4] = {0.f,0.f,0.f,0.f}, p1[4] = {0.f,0.f,0.f,0.f};
        #pragma unroll
        for (int kk = 0; kk < 16; kk++) {
            float2 a = sA[k0 + kk];
            float4 ft = ftr[kk];
            p0[0] += a.x * ft.x; p0[1] += a.x * ft.y;
            p0[2] += a.x * ft.z; p0[3] += a.x * ft.w;
            p1[0] += a.y * ft.x; p1[1] += a.y * ft.y;
            p1[2] += a.y * ft.z; p1[3] += a.y * ft.w;
        }
        #pragma unroll
        for (int i = 0; i < 4; i++)
            sPp[h][J0 + i] = make_float2(p0[i], p1[i]);
        __syncthreads();

        // ---- final combine + writes (jO, hO) ----
        float ppf = qreg;
        #pragma unroll
        for (int q = 0; q < 8; q++) ppf += comp2(sPp[q][jO], hO);

        const int nxt = cur ^ 1;
        g_Pp[nxt][myrowO * HH + jO] = ppf;
        if (doTO) g_Tg[nxt][myrowO * WCP + jO] = Tval;
        const float hr = sh[pb][myrowO];
        svp[hO][jO] = hr * ppf;
        if (doTO) sqs[hO][jO] = hr * Tval;
        // u[myrowO] = sum_j ppf * h_t[j]
        {
            float uv = ppf * sh[pb][jO];
            #pragma unroll
            for (int o = 16; o > 0; o >>= 1)
                uv += __shfl_xor_sync(0xffffffffu, uv, o);
            if ((tid & 31) == 0) sured[hO][wO] = uv;
        }
        __syncthreads();
        if (tid < HH)
            g_vpart[nxt][c][tid] = svp[0][tid] + svp[1][tid];
        else if (tid - HH < WCP)
            g_qpart[nxt][c][tid - HH] = sqs[0][tid - HH] + sqs[1][tid - HH];
        if (jO == 0)
            g_urow[nxt][myrowO] = sured[hO][0] + sured[hO][1]
                                + sured[hO][2] + sured[hO][3];

        // ---- prefetch step t+1 params (ordered by gbar's entry sync) ----
        {
            const int t1 = t + 1, nb = pb ^ 1;
            if (tid < HH) {
                sh[nb][tid] = Hw[t1 * HH + tid];
                sF[nb][tid] = make_float2(Fw[((size_t)t1 * HH + row0) * HH + tid],
                                          Fw[((size_t)t1 * HH + row0 + 1) * HH + tid]);
            } else if (tid < HH + 2) {
                sfbh[nb][tid - HH] = Fb[t1 * HH + row0 + (tid - HH)];
            } else if (tid == HH + 2) {
                sfbh[nb][2] = Hb[t1];
            }
        }

        gbar(nbar++);
        cur ^= 1; pb ^= 1;
    }

    // ---- materialize Wcf = T_63 - (u/S) q~^T  (jO, hO layout) ----
    {
        const float hb63 = sfbh[pb ^ 1][2];
        const float uj = g_urow[cur][jO];
        float termS = sh[pb ^ 1][jO] * uj;
        #pragma unroll
        for (int o = 16; o > 0; o >>= 1)
            termS += __shfl_xor_sync(0xffffffffu, termS, o);
        if ((tid & 31) == 0) sred[hO][0][wO] = termS;
        float qs = 0.f;
        if (doTO) {
            const int cc0 = hO * 32;
            #pragma unroll
            for (int i = 0; i < 32; i++) qs += g_qpart[cur][cc0 + i][jO];
            sqs[hO][jO] = qs;
        }
        __syncthreads();
        const float S = R0 + sred[hO][0][0] + sred[hO][0][1]
                           + sred[hO][0][2] + sred[hO][0][3];
        if (doTO) {
            const float Krow = g_urow[cur][myrowO] / S;
            const float qt = sqs[0][jO] + sqs[1][jO]
                           + (jO == 0 ? hb63 : 0.f) - (jO == LBn ? 1.f : 0.f);
            g_Wcf[myrowO * WCP + jO] = g_Tg[cur][myrowO * WCP + jO] - Krow * qt;
        }
    }
}

// ---------------------------------------------------------------------------
// Kernel 3: prediction chains — CTA m computes V row m with NO grid barriers.
// Also resets the grid-barrier state for the next graph replay.
// ---------------------------------------------------------------------------
__global__ void __launch_bounds__(256) pred_chains(
    const float* __restrict__ Fw, const float* __restrict__ Fb,
    const float* __restrict__ Hw, const float* __restrict__ Hb)
{
    const int m = blockIdx.x;
    const int tid = threadIdx.x;
    const int j = tid & 127, h = tid >> 7;
    const int k0 = h * 64;

    if (m == 0 && tid == 0) { g_gen = 0u; g_cnt = 0u; }

    __shared__ float r[2][HH];
    __shared__ float rp[2][HH];
    __shared__ float sfb[HH];
    __shared__ float sbias[2];

    if (tid < HH) r[0][tid] = Hw[(LBn + m) * HH + tid];
    float bias = Hb[LBn + m];
    __syncthreads();

    int rb = 0;
    for (int i = LBn + m; i >= LBn; --i) {
        if (tid < HH) sfb[tid] = Fb[i * HH + tid];
        __syncthreads();
        float rn = 0.f, bp = 0.f;
        const float* Fi = Fw + (size_t)i * HH * HH + (size_t)k0 * HH + j;
        #pragma unroll 16
        for (int kk = 0; kk < 64; kk++) {
            float rk = r[rb][k0 + kk];
            rn += Fi[kk * HH] * rk;
            bp += sfb[k0 + kk] * rk;
        }
        rp[h][j] = rn;
        if (j == 0) sbias[h] = bp;
        __syncthreads();
        if (tid < HH) r[rb ^ 1][tid] = rp[0][tid] + rp[1][tid];
        bias += sbias[0] + sbias[1];
        __syncthreads();
        rb ^= 1;
    }

    if (j < WC) {
        float vn = 0.f;
        const float* Wf = g_Wcf + (size_t)k0 * WCP + j;
        #pragma unroll 16
        for (int kk = 0; kk < 64; kk++)
            vn += Wf[kk * WCP] * r[rb][k0 + kk];
        rp[h][j] = vn;
    }
    __syncthreads();
    if (tid < WC) {
        float s = rp[0][tid] + rp[1][tid];
        if (tid == 0) s += bias;
        g_V[m][tid] = s;
    }
}

// ---------------------------------------------------------------------------
// Kernel 4: out[b][p] = V[p][0] + sum_t V[p][1+t] x[b][t]
// ---------------------------------------------------------------------------
__global__ void __launch_bounds__(256) out_gemm(
    const float* __restrict__ x, float* __restrict__ out)
{
    __shared__ float sV[PWn][WC];
    __shared__ float sx[8][LBn];
    const int tid = threadIdx.x;
    const int b0 = blockIdx.x * 8;

    for (int e = tid; e < PWn * WC; e += 256) {
        int p = e / WC, jj = e % WC;
        sV[p][jj] = g_V[p][jj];
    }
    if (tid < 128) {
        const int row = tid >> 4, seg = tid & 15;
        float4 v = *(const float4*)(x + (size_t)(b0 + row) * LBn + seg * 4);
        sx[row][seg * 4 + 0] = v.x; sx[row][seg * 4 + 1] = v.y;
        sx[row][seg * 4 + 2] = v.z; sx[row][seg * 4 + 3] = v.w;
    }
    __syncthreads();

    const int w = tid >> 5, p = tid & 31;
    float acc = sV[p][0];
    #pragma unroll 16
    for (int tt = 0; tt < LBn; tt++)
        acc += sV[p][1 + tt] * sx[w][tt];
    out[(size_t)(b0 + w) * PWn + p] = acc;
}

// ---------------------------------------------------------------------------
extern "C" void kernel_launch(void* const* d_in, const int* in_sizes, int n_in,
                              void* d_out, int out_size) {
    const float* x   = (const float*)d_in[0];
    const float* Fw  = (const float*)d_in[1];
    const float* Fb  = (const float*)d_in[2];
    const float* Hw  = (const float*)d_in[3];
    const float* Hb  = (const float*)d_in[4];
    const float* ist = (const float*)d_in[5];
    const float* icv = (const float*)d_in[6];
    const float* Q   = (const float*)d_in[7];
    const float* R   = (const float*)d_in[8];

    dim3 tgrid(WLn, 4);
    transpose_f<<<tgrid, 256>>>(Fw);
    kalman_persist<<<NCTA, TPB>>>(Fw, Fb, Hw, Hb, ist, icv, Q, R);
    pred_chains<<<PWn, 256>>>(Fw, Fb, Hw, Hb);
    out_gemm<<<8192 / 8, 256>>>(x, (float*)d_out);
}